// round 1
// baseline (speedup 1.0000x reference)
#include <cuda_runtime.h>
#include <cuda_bf16.h>
#include <math.h>

// Problem constants
#define BATCH 8
#define TSEQ  4096
#define HDIM  1024
#define SDIM  16
#define MROWS (BATCH * TSEQ)   // 32768
#define LN_EPS 1e-5f

// ---------------------------------------------------------------------------
// Scratch (device globals; no allocation allowed)
// ---------------------------------------------------------------------------
__device__ float g_xp[(size_t)MROWS * HDIM];   // x @ W_in + b_in
__device__ float g_t [(size_t)MROWS * HDIM];   // tanh(...) intermediate
__device__ float g_Wg[HDIM * 48];              // [W_B@B_mat | W_ig | W_fg]
__device__ float g_bg[48];
__device__ float g_bx[(size_t)MROWS * SDIM];
__device__ float g_ig[(size_t)MROWS * SDIM];
__device__ float g_fg[(size_t)MROWS * SDIM];
__device__ float g_hs[(size_t)MROWS * SDIM];

// ---------------------------------------------------------------------------
// Prep: fold W_B @ B_mat into combined gate weight [HDIM, 48]
// cols 0..15 = W_B@B_mat, 16..31 = W_ig, 32..47 = W_fg
// ---------------------------------------------------------------------------
__global__ void prep_w_kernel(const float* __restrict__ W_B,
                              const float* __restrict__ B_mat,
                              const float* __restrict__ W_ig,
                              const float* __restrict__ W_fg)
{
    int h = blockIdx.x;
    int j = threadIdx.x;  // 0..47
    if (j < 16) {
        float s = 0.f;
        const float* wb = W_B + (size_t)h * HDIM;
        for (int k = 0; k < HDIM; k++)
            s += wb[k] * B_mat[k * SDIM + j];
        g_Wg[h * 48 + j] = s;
    } else if (j < 32) {
        g_Wg[h * 48 + j] = W_ig[h * SDIM + (j - 16)];
    } else {
        g_Wg[h * 48 + j] = W_fg[h * SDIM + (j - 32)];
    }
}

__global__ void prep_b_kernel(const float* __restrict__ b_B,
                              const float* __restrict__ B_mat,
                              const float* __restrict__ b_ig,
                              const float* __restrict__ b_fg)
{
    int j = threadIdx.x;  // 0..47
    if (j < 16) {
        float s = 0.f;
        for (int k = 0; k < HDIM; k++)
            s += b_B[k] * B_mat[k * SDIM + j];
        g_bg[j] = s;
    } else if (j < 32) {
        g_bg[j] = b_ig[j - 16];
    } else {
        g_bg[j] = b_fg[j - 32];
    }
}

// ---------------------------------------------------------------------------
// Main GEMM: C[M,N] = A[M,K] @ W[K,N] + bias, templated epilogue.
//  EPI 0: plain (xp = x@W_in + b_in)
//  EPI 1: C = tanh(acc + bias + hs_row @ C_mat)        (d -> t)
//  EPI 2: C = acc + bias + resid                        (out pre-LN)
// BM=BN=128, BK=16, TM=TN=8, 256 threads. M,N,K all divisible -> no bounds.
// ---------------------------------------------------------------------------
#define BM 128
#define BN 128
#define BK 16
#define TM 8
#define TN 8

template<int EPI>
__global__ void __launch_bounds__(256)
gemm_kernel(const float* __restrict__ A, const float* __restrict__ W,
            const float* __restrict__ bias, float* __restrict__ C,
            const float* __restrict__ hs,   // EPI1: [M,16]
            const float* __restrict__ Cm,   // EPI1: [16,N] (C_mat)
            const float* __restrict__ resid,// EPI2: [M,N]
            int M, int N, int K)
{
    __shared__ float As[BK][BM];
    __shared__ float Bs[BK][BN];
    __shared__ float hsS[BM][SDIM];
    __shared__ float CmS[SDIM][BN];

    const int tid = threadIdx.x;
    const int m0 = blockIdx.y * BM;
    const int n0 = blockIdx.x * BN;

    if (EPI == 1) {
        for (int i = tid; i < BM * SDIM; i += 256) {
            int r = i >> 4, c = i & 15;
            hsS[r][c] = hs[(size_t)(m0 + r) * SDIM + c];
        }
        for (int i = tid; i < SDIM * BN; i += 256) {
            int r = i >> 7, c = i & 127;
            CmS[r][c] = Cm[(size_t)r * N + n0 + c];
        }
    }

    float acc[TM][TN];
#pragma unroll
    for (int i = 0; i < TM; i++)
#pragma unroll
        for (int j = 0; j < TN; j++) acc[i][j] = 0.f;

    const int a_r = tid >> 2;          // 0..63
    const int a_c = (tid & 3) << 2;    // 0,4,8,12
    const int b_r = tid >> 5;          // 0..7
    const int b_c = (tid & 31) << 2;   // 0..124
    const int ty = tid >> 4;           // 0..15
    const int tx = tid & 15;           // 0..15

    for (int k0 = 0; k0 < K; k0 += BK) {
        float4 a0 = *(const float4*)&A[(size_t)(m0 + a_r) * K + k0 + a_c];
        float4 a1 = *(const float4*)&A[(size_t)(m0 + a_r + 64) * K + k0 + a_c];
        float4 w0 = *(const float4*)&W[(size_t)(k0 + b_r) * N + n0 + b_c];
        float4 w1 = *(const float4*)&W[(size_t)(k0 + b_r + 8) * N + n0 + b_c];
        __syncthreads();
        As[a_c + 0][a_r] = a0.x; As[a_c + 1][a_r] = a0.y;
        As[a_c + 2][a_r] = a0.z; As[a_c + 3][a_r] = a0.w;
        As[a_c + 0][a_r + 64] = a1.x; As[a_c + 1][a_r + 64] = a1.y;
        As[a_c + 2][a_r + 64] = a1.z; As[a_c + 3][a_r + 64] = a1.w;
        *(float4*)&Bs[b_r][b_c] = w0;
        *(float4*)&Bs[b_r + 8][b_c] = w1;
        __syncthreads();
#pragma unroll
        for (int kk = 0; kk < BK; kk++) {
            float a[TM], b[TN];
#pragma unroll
            for (int i = 0; i < TM; i++) a[i] = As[kk][ty * TM + i];
#pragma unroll
            for (int j = 0; j < TN; j++) b[j] = Bs[kk][tx * TN + j];
#pragma unroll
            for (int i = 0; i < TM; i++)
#pragma unroll
                for (int j = 0; j < TN; j++)
                    acc[i][j] += a[i] * b[j];
        }
    }

#pragma unroll
    for (int i = 0; i < TM; i++) {
        const int mr = ty * TM + i;
        const int m = m0 + mr;
#pragma unroll
        for (int j = 0; j < TN; j++) {
            const int nc = tx * TN + j;
            const int n = n0 + nc;
            float v = acc[i][j] + bias[n];
            if (EPI == 1) {
                float e = 0.f;
#pragma unroll
                for (int s = 0; s < SDIM; s++)
                    e += hsS[mr][s] * CmS[s][nc];
                v = tanhf(v + e);
            }
            if (EPI == 2) {
                v += resid[(size_t)m * N + n];
            }
            C[(size_t)m * N + n] = v;
        }
    }
}

// ---------------------------------------------------------------------------
// Gates: g = xp @ Wg[1024,48] + bg ; split into Bx, sigmoid(ig), sigmoid(fg)
// One block = 16 rows x 48 cols, 256 threads (row = tid/16, col = tid%16,
// each thread owns cols col, col+16, col+32).
// ---------------------------------------------------------------------------
#define GT_M 16
#define GT_K 64

__global__ void __launch_bounds__(256)
gates_kernel(const float* __restrict__ xp)
{
    __shared__ float At[GT_M][GT_K + 1];
    __shared__ float Wc[GT_K][49];

    const int tid = threadIdx.x;
    const int m0 = blockIdx.x * GT_M;
    const int row = tid >> 4;
    const int col = tid & 15;

    float a0 = 0.f, a1 = 0.f, a2 = 0.f;

    for (int k0 = 0; k0 < HDIM; k0 += GT_K) {
        {
            int i = tid * 4;
            int r = i >> 6, c = i & 63;
            float4 v = *(const float4*)&xp[(size_t)(m0 + r) * HDIM + k0 + c];
            At[r][c + 0] = v.x; At[r][c + 1] = v.y;
            At[r][c + 2] = v.z; At[r][c + 3] = v.w;
        }
        for (int i = tid; i < GT_K * 48; i += 256) {
            int r = i / 48, c = i % 48;
            Wc[r][c] = g_Wg[(k0 + r) * 48 + c];
        }
        __syncthreads();
#pragma unroll 8
        for (int kk = 0; kk < GT_K; kk++) {
            float a = At[row][kk];
            a0 += a * Wc[kk][col];
            a1 += a * Wc[kk][col + 16];
            a2 += a * Wc[kk][col + 32];
        }
        __syncthreads();
    }

    const size_t o = (size_t)(m0 + row) * SDIM + col;
    g_bx[o] = a0 + g_bg[col];
    g_ig[o] = 1.f / (1.f + expf(-(a1 + g_bg[col + 16])));
    g_fg[o] = 1.f / (1.f + expf(-(a2 + g_bg[col + 32])));
}

// ---------------------------------------------------------------------------
// Sequential recurrence: h_t = fg_t * h_{t-1} + ig_t * bx_t  (128 chains)
// ---------------------------------------------------------------------------
__global__ void recur_kernel()
{
    const int tid = threadIdx.x;  // 0..127
    const int b = tid >> 4;
    const int s = tid & 15;
    size_t base = (size_t)b * TSEQ * SDIM + s;
    float h = 0.f;
#pragma unroll 4
    for (int t = 0; t < TSEQ; t++) {
        size_t idx = base + (size_t)t * SDIM;
        h = g_fg[idx] * h + g_ig[idx] * g_bx[idx];
        g_hs[idx] = h;
    }
}

// ---------------------------------------------------------------------------
// LayerNorm (in place on d_out): one block per row of 1024
// ---------------------------------------------------------------------------
__global__ void __launch_bounds__(256)
ln_kernel(float* __restrict__ y,
          const float* __restrict__ gamma, const float* __restrict__ beta)
{
    const int m = blockIdx.x;
    const int tid = threadIdx.x;
    float4 v = ((const float4*)(y + (size_t)m * HDIM))[tid];

    float s = v.x + v.y + v.z + v.w;
    float q = v.x * v.x + v.y * v.y + v.z * v.z + v.w * v.w;

    // warp reduce
#pragma unroll
    for (int o = 16; o > 0; o >>= 1) {
        s += __shfl_xor_sync(0xFFFFFFFFu, s, o);
        q += __shfl_xor_sync(0xFFFFFFFFu, q, o);
    }
    __shared__ float rs[8], rq[8];
    const int wid = tid >> 5, lid = tid & 31;
    if (lid == 0) { rs[wid] = s; rq[wid] = q; }
    __syncthreads();
    if (wid == 0) {
        float ss = (lid < 8) ? rs[lid] : 0.f;
        float qq = (lid < 8) ? rq[lid] : 0.f;
#pragma unroll
        for (int o = 4; o > 0; o >>= 1) {
            ss += __shfl_xor_sync(0xFFFFFFFFu, ss, o);
            qq += __shfl_xor_sync(0xFFFFFFFFu, qq, o);
        }
        if (lid == 0) { rs[0] = ss; rq[0] = qq; }
    }
    __syncthreads();
    const float mu = rs[0] * (1.f / HDIM);
    const float var = rq[0] * (1.f / HDIM) - mu * mu;
    const float inv = rsqrtf(var + LN_EPS);

    float4 g = ((const float4*)gamma)[tid];
    float4 be = ((const float4*)beta)[tid];
    float4 o4;
    o4.x = (v.x - mu) * inv * g.x + be.x;
    o4.y = (v.y - mu) * inv * g.y + be.y;
    o4.z = (v.z - mu) * inv * g.z + be.z;
    o4.w = (v.w - mu) * inv * g.w + be.w;
    ((float4*)(y + (size_t)m * HDIM))[tid] = o4;
}

// ---------------------------------------------------------------------------
// Launch
// ---------------------------------------------------------------------------
extern "C" void kernel_launch(void* const* d_in, const int* in_sizes, int n_in,
                              void* d_out, int out_size)
{
    const float* x     = (const float*)d_in[0];
    const float* W_in  = (const float*)d_in[1];
    const float* b_in  = (const float*)d_in[2];
    const float* B_mat = (const float*)d_in[3];
    const float* C_mat = (const float*)d_in[4];
    const float* W_B   = (const float*)d_in[5];
    const float* b_B   = (const float*)d_in[6];
    const float* W_D   = (const float*)d_in[7];
    const float* b_D   = (const float*)d_in[8];
    const float* W_out = (const float*)d_in[9];
    const float* b_out = (const float*)d_in[10];
    const float* W_ig  = (const float*)d_in[11];
    const float* b_ig  = (const float*)d_in[12];
    const float* W_fg  = (const float*)d_in[13];
    const float* b_fg  = (const float*)d_in[14];
    const float* gamma = (const float*)d_in[15];
    const float* beta  = (const float*)d_in[16];
    float* out = (float*)d_out;

    const int M = in_sizes[0] / HDIM;  // 32768

    float *xp_p, *t_p, *hs_p;
    cudaGetSymbolAddress((void**)&xp_p, g_xp);
    cudaGetSymbolAddress((void**)&t_p,  g_t);
    cudaGetSymbolAddress((void**)&hs_p, g_hs);

    // prep: fold W_B @ B_mat, assemble gate weights
    prep_w_kernel<<<HDIM, 48>>>(W_B, B_mat, W_ig, W_fg);
    prep_b_kernel<<<1, 48>>>(b_B, B_mat, b_ig, b_fg);

    dim3 gg(HDIM / BN, M / BM);

    // GEMM1: xp = x @ W_in + b_in
    gemm_kernel<0><<<gg, 256>>>(x, W_in, b_in, xp_p,
                                nullptr, nullptr, nullptr, M, HDIM, HDIM);

    // gates: Bx, ig, fg
    gates_kernel<<<M / GT_M, 256>>>(xp_p);

    // sequential recurrence
    recur_kernel<<<1, 128>>>();

    // GEMM2: t = tanh(xp @ W_D + b_D + hs @ C_mat)
    gemm_kernel<1><<<gg, 256>>>(xp_p, W_D, b_D, t_p,
                                hs_p, C_mat, nullptr, M, HDIM, HDIM);

    // GEMM3: out = t @ W_out + b_out + xp
    gemm_kernel<2><<<gg, 256>>>(t_p, W_out, b_out, out,
                                nullptr, nullptr, xp_p, M, HDIM, HDIM);

    // LayerNorm in place
    ln_kernel<<<M, 256>>>(out, gamma, beta);
}